// round 5
// baseline (speedup 1.0000x reference)
#include <cuda_runtime.h>
#include <cuda_fp16.h>
#include <stdint.h>

// ---------------- problem constants ----------------
#define HID     2048
#define BATCHN  64
#define G4      8192
#define NSTEPS  30
#define NTILE   128           // M tiles of 64 gate-rows -> 128 CTAs (persistent)
#define NKCH    32            // K chunks of 64 fp16 (128B rows, SW128)
#define WCH     8192          // bytes per W chunk tile (64 rows x 128B)
#define HCH     8192          // bytes per h chunk tile (64 batch x 128B)
#define STG     16384         // stage = W 8K + h 8K
#define NSTG    4
#define SMEM_REQ (NSTG*STG + 1024)

// ---------------- device scratch (static, no allocs) ----------------
__device__ __align__(1024) unsigned char g_wsum[NTILE*NKCH*WCH]; // 32MB fp16 (Wih+Whh)
__device__ __align__(1024) unsigned char g_whh [NTILE*NKCH*WCH]; // 32MB fp16 (Whh, step 0)
__device__ __align__(1024) unsigned char g_hA[NKCH*HCH];         // 256KB tiled fp16 h
__device__ __align__(1024) unsigned char g_hB[NKCH*HCH];
__device__ float g_c[BATCHN*HID];
__device__ float g_bias[G4];
__device__ float g_hist[NSTEPS*BATCHN*HID];
__device__ unsigned g_barrier;

// ---------------- helpers ----------------
__device__ __forceinline__ uint32_t smem_u32(const void* p) {
    uint32_t a;
    asm("{ .reg .u64 t; cvta.to.shared.u64 t, %1; cvt.u32.u64 %0, t; }" : "=r"(a) : "l"(p));
    return a;
}
__device__ __forceinline__ uint32_t swz(uint32_t o) { return o ^ ((o >> 3) & 0x70); }

__device__ __forceinline__ void ldm4(uint32_t* r, uint32_t a) {
    asm volatile("ldmatrix.sync.aligned.m8n8.x4.shared.b16 {%0,%1,%2,%3}, [%4];"
                 : "=r"(r[0]), "=r"(r[1]), "=r"(r[2]), "=r"(r[3]) : "r"(a));
}
__device__ __forceinline__ void mma16816(float* d, const uint32_t* a, uint32_t b0, uint32_t b1) {
    asm volatile("mma.sync.aligned.m16n8k16.row.col.f32.f16.f16.f32 "
                 "{%0,%1,%2,%3}, {%4,%5,%6,%7}, {%8,%9}, {%0,%1,%2,%3};"
                 : "+f"(d[0]), "+f"(d[1]), "+f"(d[2]), "+f"(d[3])
                 : "r"(a[0]), "r"(a[1]), "r"(a[2]), "r"(a[3]), "r"(b0), "r"(b1));
}
__device__ __forceinline__ void cp16(uint32_t dst, const void* src) {
    asm volatile("cp.async.cg.shared.global [%0], [%1], 16;" :: "r"(dst), "l"(src) : "memory");
}
__device__ __forceinline__ float sigm(float x) {
    x = fminf(15.f, fmaxf(-15.f, x));
    return 1.f / (1.f + __expf(-x));
}
__device__ __forceinline__ float tanh_(float x) {
    x = fminf(8.f, fmaxf(-8.f, x));
    float e = __expf(-2.f * x);
    return (1.f - e) / (1.f + e);
}

// ---------------- prep: tiled + SW128-swizzled fp16 weights ----------------
// Tile t (0..127), row r (0..63): gate = r>>4, unit = r&15 -> orig row gate*HID + t*16 + unit.
__global__ void prep_weights(const float* __restrict__ Wih, const float* __restrict__ Whh) {
    int id  = blockIdx.x * 256 + threadIdx.x;     // 8,388,608 (one half2 each)
    int cp  = id & 31;
    int row = (id >> 5) & 63;
    int kc  = (id >> 11) & 31;
    int t   = id >> 16;
    int gate = row >> 4, u = row & 15;
    long orow = (long)gate * HID + t * 16 + u;
    int  ocol = kc * 64 + cp * 2;
    float2 wi = *(const float2*)(Wih + orow * HID + ocol);
    float2 wh = *(const float2*)(Whh + orow * HID + ocol);
    uint32_t toff = (uint32_t)(t * NKCH + kc) * WCH + swz((uint32_t)(row * 128 + cp * 4));
    *(__half2*)(g_wsum + toff) =
        __halves2half2(__float2half_rn(wi.x + wh.x), __float2half_rn(wi.y + wh.y));
    *(__half2*)(g_whh + toff) =
        __halves2half2(__float2half_rn(wh.x), __float2half_rn(wh.y));
}

// zero c + barrier, fused bias, tiled fp16 h0 into buffer A
__global__ void prep_misc(const float* __restrict__ tok,
                          const float* __restrict__ bih, const float* __restrict__ bhh) {
    int id = blockIdx.x * 256 + threadIdx.x;      // 131072
    float h0 = tok[id];
    g_c[id] = 0.0f;
    int b = id >> 11, hid = id & 2047;
    int kc = hid >> 6, cc = hid & 63;
    uint32_t off = (uint32_t)kc * HCH + swz((uint32_t)(b * 128 + cc * 2));
    *(__half*)(g_hA + off) = __float2half_rn(h0);
    if (id < G4) g_bias[id] = bih[id] + bhh[id];
    if (id == 0) g_barrier = 0u;
}

// ---------------- persistent kernel: all 30 LSTM steps ----------------
#define SMX(g, b, u) smx[((g) * 64 + (b)) * 17 + (u)]

__global__ void __launch_bounds__(128, 1) lstm_persist() {
    extern __shared__ unsigned char smraw[];
    uint32_t sbr  = smem_u32(smraw);
    uint32_t base = (sbr + 1023) & ~1023u;
    float* smx = (float*)(smraw + (base - sbr));   // overlaps stages 0-1 (17.4KB)

    int tid = threadIdx.x;
    int lane = tid & 31, wid = tid >> 5;
    int warp_m = wid & 1;        // M half (32 rows = 2 gates)
    int warp_n = wid >> 1;       // N half (32 batch)
    int blk = blockIdx.x;

    // ldmatrix lane address components
    uint32_t a_colb = (uint32_t)((lane >> 4) << 4);
    uint32_t a_r0   = (uint32_t)(warp_m * 32 + (lane & 15));
    uint32_t b_row  = (uint32_t)(warp_n * 32 + (lane & 7) + ((lane >> 4) << 3));
    uint32_t b_colb = (uint32_t)(((lane >> 3) & 1) << 4);

    const unsigned char* wsum_t = g_wsum + (size_t)blk * NKCH * WCH;
    const unsigned char* whh_t  = g_whh  + (size_t)blk * NKCH * WCH;

    for (int step = 0; step < NSTEPS; step++) {
        const unsigned char* wsrc = step ? wsum_t : whh_t;
        const unsigned char* hsrc = (step & 1) ? g_hB : g_hA;
        unsigned char*       hout = (step & 1) ? g_hA : g_hB;

        float acc[2][16];
        #pragma unroll
        for (int i = 0; i < 2; i++)
            #pragma unroll
            for (int j = 0; j < 16; j++) acc[i][j] = 0.f;

        // prefetch chunks 0..2
        #pragma unroll
        for (int c = 0; c < 3; c++) {
            uint32_t sb = base + (uint32_t)c * STG;
            #pragma unroll
            for (int r = 0; r < 4; r++) {
                int o = (r * 128 + tid) * 16;
                cp16(sb + o,        wsrc + (size_t)c * WCH + o);
                cp16(sb + 8192 + o, hsrc + (size_t)c * HCH + o);
            }
            asm volatile("cp.async.commit_group;" ::: "memory");
        }

        for (int kc = 0; kc < NKCH; kc++) {
            if (kc <= 29)      asm volatile("cp.async.wait_group 2;" ::: "memory");
            else if (kc == 30) asm volatile("cp.async.wait_group 1;" ::: "memory");
            else               asm volatile("cp.async.wait_group 0;" ::: "memory");
            __syncthreads();

            int nc = kc + 3;
            if (nc < NKCH) {
                uint32_t sb = base + (uint32_t)(nc & 3) * STG;
                #pragma unroll
                for (int r = 0; r < 4; r++) {
                    int o = (r * 128 + tid) * 16;
                    cp16(sb + o,        wsrc + (size_t)nc * WCH + o);
                    cp16(sb + 8192 + o, hsrc + (size_t)nc * HCH + o);
                }
                asm volatile("cp.async.commit_group;" ::: "memory");
            }

            uint32_t sw = base + (uint32_t)(kc & 3) * STG;
            uint32_t sh = sw + 8192;
            #pragma unroll
            for (int ks = 0; ks < 4; ks++) {
                uint32_t a0[4], a1[4], bb[8];
                ldm4(a0, sw + swz(a_r0 * 128 + (uint32_t)ks * 32 + a_colb));
                ldm4(a1, sw + swz((a_r0 + 16) * 128 + (uint32_t)ks * 32 + a_colb));
                ldm4(bb,     sh + swz(b_row * 128 + (uint32_t)ks * 32 + b_colb));
                ldm4(bb + 4, sh + swz((b_row + 16) * 128 + (uint32_t)ks * 32 + b_colb));
                #pragma unroll
                for (int g = 0; g < 4; g++) {
                    mma16816(acc[0] + 4 * g, a0, bb[2 * g], bb[2 * g + 1]);
                    mma16816(acc[1] + 4 * g, a1, bb[2 * g], bb[2 * g + 1]);
                }
            }
        }
        __syncthreads();

        // ---- exchange: smx[gate][batch][unit] ----
        #pragma unroll
        for (int mt = 0; mt < 2; mt++) {
            int gate = warp_m * 2 + mt;
            #pragma unroll
            for (int g = 0; g < 4; g++) {
                int n0 = warp_n * 32 + 8 * g + 2 * (lane & 3);
                int u0 = lane >> 2;
                SMX(gate, n0,     u0    ) = acc[mt][4 * g + 0];
                SMX(gate, n0 + 1, u0    ) = acc[mt][4 * g + 1];
                SMX(gate, n0,     u0 + 8) = acc[mt][4 * g + 2];
                SMX(gate, n0 + 1, u0 + 8) = acc[mt][4 * g + 3];
            }
        }
        __syncthreads();

        // ---- fused LSTM cell: 16 units x 64 batch per CTA ----
        int kcb = blk >> 2;                 // h chunk this CTA's units land in
        #pragma unroll
        for (int k = 0; k < 8; k++) {
            int p = k * 128 + tid;          // (unit, batch)
            int u = p & 15, b = p >> 4;
            int hid = blk * 16 + u;
            float xi = SMX(0, b, u) + g_bias[hid];
            float xf = SMX(1, b, u) + g_bias[2048 + hid];
            float xg = SMX(2, b, u) + g_bias[4096 + hid];
            float xo = SMX(3, b, u) + g_bias[6144 + hid];
            float ii = sigm(xi), ff = sigm(xf), gg = tanh_(xg), oo = sigm(xo);
            int ci = b * HID + hid;
            float c = ff * g_c[ci] + ii * gg;
            g_c[ci] = c;
            float h = oo * tanh_(c);
            g_hist[((size_t)step * BATCHN + b) * HID + hid] = h;
            uint32_t off = (uint32_t)kcb * HCH +
                           swz((uint32_t)(b * 128 + ((blk & 3) * 16 + u) * 2));
            *(__half*)(hout + off) = __float2half_rn(h);
        }

        // ---- grid-wide barrier (all 128 CTAs resident) ----
        __threadfence();
        __syncthreads();
        if (tid == 0) {
            atomicAdd(&g_barrier, 1u);
            unsigned target = 128u * (unsigned)(step + 1);
            while (*(volatile unsigned*)&g_barrier < target) __nanosleep(64);
            __threadfence();
        }
        __syncthreads();
    }
}

// ---------------- output projection: y[b,t] = hist[t,b,:] . W_out + b_out ----------------
__global__ void out_kernel(const float* __restrict__ Wout, const float* __restrict__ bout,
                           float* __restrict__ out) {
    int t = blockIdx.x / BATCHN;
    int b = blockIdx.x % BATCHN;
    const float* h = g_hist + ((size_t)t * BATCHN + b) * HID;
    float acc = 0.f;
    for (int k = threadIdx.x; k < HID; k += 128) acc += h[k] * Wout[k];
    #pragma unroll
    for (int o = 16; o; o >>= 1) acc += __shfl_xor_sync(0xFFFFFFFFu, acc, o);
    __shared__ float ws[4];
    if ((threadIdx.x & 31) == 0) ws[threadIdx.x >> 5] = acc;
    __syncthreads();
    if (threadIdx.x == 0)
        out[b * NSTEPS + t] = ws[0] + ws[1] + ws[2] + ws[3] + bout[0];
}

// ---------------- launch ----------------
extern "C" void kernel_launch(void* const* d_in, const int* in_sizes, int n_in,
                              void* d_out, int out_size) {
    int wi = (n_in >= 8) ? 2 : 1;   // skip scalar `steps` input if present
    const float* tok  = (const float*)d_in[0];
    const float* Wih  = (const float*)d_in[wi];
    const float* Whh  = (const float*)d_in[wi + 1];
    const float* bih  = (const float*)d_in[wi + 2];
    const float* bhh  = (const float*)d_in[wi + 3];
    const float* Wout = (const float*)d_in[wi + 4];
    const float* bout = (const float*)d_in[wi + 5];
    float* out = (float*)d_out;

    cudaFuncSetAttribute(lstm_persist, cudaFuncAttributeMaxDynamicSharedMemorySize, SMEM_REQ);

    prep_weights<<<32768, 256>>>(Wih, Whh);
    prep_misc<<<512, 256>>>(tok, bih, bhh);
    lstm_persist<<<NTILE, 128, SMEM_REQ>>>();
    out_kernel<<<NSTEPS * BATCHN, 128>>>(Wout, bout, out);
}

// round 6
// speedup vs baseline: 1.5148x; 1.5148x over previous
#include <cuda_runtime.h>
#include <cuda_fp16.h>
#include <stdint.h>

// ---------------- problem constants ----------------
#define HID     2048
#define BATCHN  64
#define G4      8192
#define NSTEPS  30
#define NTILE   128           // M tiles of 64 gate-rows -> 128 CTAs
#define NKCH    32            // K chunks of 64 fp16 (128B rows, SW128)
#define WCH     8192          // bytes per W chunk tile (64 rows x 128B)
#define HCH     8192          // bytes per h chunk tile (64 batch x 128B)
#define STG     16384         // stage = W 8K + h 8K
#define NSTG    4
#define SMEM_REQ (NSTG*STG + 1024)

// ---------------- device scratch (static, no allocs) ----------------
__device__ __align__(1024) unsigned char g_wsum[NTILE*NKCH*WCH]; // 32MB fp16 (Wih+Whh)
__device__ __align__(1024) unsigned char g_whh [NTILE*NKCH*WCH]; // 32MB fp16 (Whh, step 0)
__device__ __align__(1024) unsigned char g_hA[NKCH*HCH];         // 256KB tiled fp16 h
__device__ __align__(1024) unsigned char g_hB[NKCH*HCH];
__device__ float g_c[BATCHN*HID];
__device__ float g_bias[G4];
__device__ float g_hist[NSTEPS*BATCHN*HID];

// ---------------- helpers ----------------
__device__ __forceinline__ uint32_t smem_u32(const void* p) {
    uint32_t a;
    asm("{ .reg .u64 t; cvta.to.shared.u64 t, %1; cvt.u32.u64 %0, t; }" : "=r"(a) : "l"(p));
    return a;
}
__device__ __forceinline__ uint32_t swz(uint32_t o) { return o ^ ((o >> 3) & 0x70); }

__device__ __forceinline__ void ldm4(uint32_t* r, uint32_t a) {
    asm volatile("ldmatrix.sync.aligned.m8n8.x4.shared.b16 {%0,%1,%2,%3}, [%4];"
                 : "=r"(r[0]), "=r"(r[1]), "=r"(r[2]), "=r"(r[3]) : "r"(a));
}
__device__ __forceinline__ void mma16816(float* d, const uint32_t* a, uint32_t b0, uint32_t b1) {
    asm volatile("mma.sync.aligned.m16n8k16.row.col.f32.f16.f16.f32 "
                 "{%0,%1,%2,%3}, {%4,%5,%6,%7}, {%8,%9}, {%0,%1,%2,%3};"
                 : "+f"(d[0]), "+f"(d[1]), "+f"(d[2]), "+f"(d[3])
                 : "r"(a[0]), "r"(a[1]), "r"(a[2]), "r"(a[3]), "r"(b0), "r"(b1));
}
__device__ __forceinline__ void cp16(uint32_t dst, const void* src) {
    asm volatile("cp.async.cg.shared.global [%0], [%1], 16;" :: "r"(dst), "l"(src) : "memory");
}
__device__ __forceinline__ float sigm(float x) {
    x = fminf(15.f, fmaxf(-15.f, x));
    return 1.f / (1.f + __expf(-x));
}
__device__ __forceinline__ float tanh_(float x) {
    x = fminf(8.f, fmaxf(-8.f, x));
    float e = __expf(-2.f * x);
    return (1.f - e) / (1.f + e);
}

// ---------------- prep: tiled + SW128-swizzled fp16 weights ----------------
// Tile t (0..127), row r (0..63): gate = r>>4, unit = r&15 -> orig row gate*HID + t*16 + unit.
__global__ void prep_weights(const float* __restrict__ Wih, const float* __restrict__ Whh) {
    int id  = blockIdx.x * 256 + threadIdx.x;     // 8,388,608 (one half2 each)
    int cp  = id & 31;
    int row = (id >> 5) & 63;
    int kc  = (id >> 11) & 31;
    int t   = id >> 16;
    int gate = row >> 4, u = row & 15;
    long orow = (long)gate * HID + t * 16 + u;
    int  ocol = kc * 64 + cp * 2;
    float2 wi = *(const float2*)(Wih + orow * HID + ocol);
    float2 wh = *(const float2*)(Whh + orow * HID + ocol);
    uint32_t toff = (uint32_t)(t * NKCH + kc) * WCH + swz((uint32_t)(row * 128 + cp * 4));
    *(__half2*)(g_wsum + toff) =
        __halves2half2(__float2half_rn(wi.x + wh.x), __float2half_rn(wi.y + wh.y));
    *(__half2*)(g_whh + toff) =
        __halves2half2(__float2half_rn(wh.x), __float2half_rn(wh.y));
}

// zero c, fused bias, tiled fp16 h0 into buffer A
__global__ void prep_misc(const float* __restrict__ tok,
                          const float* __restrict__ bih, const float* __restrict__ bhh) {
    int id = blockIdx.x * 256 + threadIdx.x;      // 131072
    float h0 = tok[id];
    g_c[id] = 0.0f;
    int b = id >> 11, hid = id & 2047;
    int kc = hid >> 6, cc = hid & 63;
    uint32_t off = (uint32_t)kc * HCH + swz((uint32_t)(b * 128 + cc * 2));
    *(__half*)(g_hA + off) = __float2half_rn(h0);
    if (id < G4) g_bias[id] = bih[id] + bhh[id];
}

// ---------------- one LSTM step ----------------
// 256 threads, warp grid 2M x 4N: warp_m in {0,1} (32 gate-rows), warp_n in {0..3} (16 batch).
#define SMX(g, b, u) smx[((g) * 64 + (b)) * 17 + (u)]

__global__ void __launch_bounds__(256, 1) lstm_step(int step) {
    extern __shared__ unsigned char smraw[];
    uint32_t sbr  = smem_u32(smraw);
    uint32_t base = (sbr + 1023) & ~1023u;
    float* smx = (float*)(smraw + (base - sbr));   // epilogue scratch, overlaps stage 0-1

    int tid = threadIdx.x;
    int lane = tid & 31, wid = tid >> 5;
    int warp_m = wid & 1;
    int warp_n = wid >> 1;
    int blk = blockIdx.x;

    const unsigned char* wsrc = ((step ? g_wsum : g_whh) + (size_t)blk * NKCH * WCH);
    const unsigned char* hsrc = (step & 1) ? g_hB : g_hA;
    unsigned char*       hout = (step & 1) ? g_hA : g_hB;

    // ldmatrix lane address components
    uint32_t a_colb = (uint32_t)((lane >> 4) << 4);
    uint32_t a_r0   = (uint32_t)(warp_m * 32 + (lane & 15));
    uint32_t b_row  = (uint32_t)(warp_n * 16 + (lane & 7) + ((lane >> 4) << 3));
    uint32_t b_colb = (uint32_t)(((lane >> 3) & 1) << 4);

    float acc[2][8];
    #pragma unroll
    for (int i = 0; i < 2; i++)
        #pragma unroll
        for (int j = 0; j < 8; j++) acc[i][j] = 0.f;

    // prefetch chunks 0..2
    #pragma unroll
    for (int c = 0; c < 3; c++) {
        uint32_t sb = base + (uint32_t)c * STG;
        #pragma unroll
        for (int r = 0; r < 2; r++) {
            int o = (r * 256 + tid) * 16;
            cp16(sb + o,        wsrc + (size_t)c * WCH + o);
            cp16(sb + 8192 + o, hsrc + (size_t)c * HCH + o);
        }
        asm volatile("cp.async.commit_group;" ::: "memory");
    }

    for (int kc = 0; kc < NKCH; kc++) {
        if (kc <= 29)      asm volatile("cp.async.wait_group 2;" ::: "memory");
        else if (kc == 30) asm volatile("cp.async.wait_group 1;" ::: "memory");
        else               asm volatile("cp.async.wait_group 0;" ::: "memory");
        __syncthreads();

        int nc = kc + 3;
        if (nc < NKCH) {
            uint32_t sb = base + (uint32_t)(nc & 3) * STG;
            #pragma unroll
            for (int r = 0; r < 2; r++) {
                int o = (r * 256 + tid) * 16;
                cp16(sb + o,        wsrc + (size_t)nc * WCH + o);
                cp16(sb + 8192 + o, hsrc + (size_t)nc * HCH + o);
            }
            asm volatile("cp.async.commit_group;" ::: "memory");
        }

        uint32_t sw = base + (uint32_t)(kc & 3) * STG;
        uint32_t sh = sw + 8192;
        #pragma unroll
        for (int ks = 0; ks < 4; ks++) {
            uint32_t a0[4], a1[4], bb[4];
            ldm4(a0, sw + swz(a_r0 * 128 + (uint32_t)ks * 32 + a_colb));
            ldm4(a1, sw + swz((a_r0 + 16) * 128 + (uint32_t)ks * 32 + a_colb));
            ldm4(bb, sh + swz(b_row * 128 + (uint32_t)ks * 32 + b_colb));
            mma16816(acc[0] + 0, a0, bb[0], bb[1]);
            mma16816(acc[0] + 4, a0, bb[2], bb[3]);
            mma16816(acc[1] + 0, a1, bb[0], bb[1]);
            mma16816(acc[1] + 4, a1, bb[2], bb[3]);
        }
    }
    __syncthreads();

    // ---- exchange: smx[gate][batch][unit] ----
    #pragma unroll
    for (int mt = 0; mt < 2; mt++) {
        int gate = warp_m * 2 + mt;
        #pragma unroll
        for (int g = 0; g < 2; g++) {
            int n0 = warp_n * 16 + 8 * g + 2 * (lane & 3);
            int u0 = lane >> 2;
            SMX(gate, n0,     u0    ) = acc[mt][4 * g + 0];
            SMX(gate, n0 + 1, u0    ) = acc[mt][4 * g + 1];
            SMX(gate, n0,     u0 + 8) = acc[mt][4 * g + 2];
            SMX(gate, n0 + 1, u0 + 8) = acc[mt][4 * g + 3];
        }
    }
    __syncthreads();

    // ---- fused LSTM cell: 16 units x 64 batch per CTA ----
    int kcb = blk >> 2;
    #pragma unroll
    for (int k = 0; k < 4; k++) {
        int p = k * 256 + tid;          // (unit, batch)
        int u = p & 15, b = p >> 4;
        int hid = blk * 16 + u;
        float xi = SMX(0, b, u) + g_bias[hid];
        float xf = SMX(1, b, u) + g_bias[2048 + hid];
        float xg = SMX(2, b, u) + g_bias[4096 + hid];
        float xo = SMX(3, b, u) + g_bias[6144 + hid];
        float ii = sigm(xi), ff = sigm(xf), gg = tanh_(xg), oo = sigm(xo);
        int ci = b * HID + hid;
        float c = ff * g_c[ci] + ii * gg;
        g_c[ci] = c;
        float h = oo * tanh_(c);
        g_hist[((size_t)step * BATCHN + b) * HID + hid] = h;
        uint32_t off = (uint32_t)kcb * HCH +
                       swz((uint32_t)(b * 128 + ((blk & 3) * 16 + u) * 2));
        *(__half*)(hout + off) = __float2half_rn(h);
    }
}

// ---------------- output projection: y[b,t] = hist[t,b,:] . W_out + b_out ----------------
__global__ void out_kernel(const float* __restrict__ Wout, const float* __restrict__ bout,
                           float* __restrict__ out) {
    int t = blockIdx.x / BATCHN;
    int b = blockIdx.x % BATCHN;
    const float4* h = (const float4*)(g_hist + ((size_t)t * BATCHN + b) * HID);
    const float4* w = (const float4*)Wout;
    float acc = 0.f;
    #pragma unroll
    for (int it = 0; it < 4; it++) {
        int k = it * 128 + threadIdx.x;
        float4 hv = h[k], wv = w[k];
        acc += hv.x * wv.x + hv.y * wv.y + hv.z * wv.z + hv.w * wv.w;
    }
    #pragma unroll
    for (int o = 16; o; o >>= 1) acc += __shfl_xor_sync(0xFFFFFFFFu, acc, o);
    __shared__ float ws[4];
    if ((threadIdx.x & 31) == 0) ws[threadIdx.x >> 5] = acc;
    __syncthreads();
    if (threadIdx.x == 0)
        out[b * NSTEPS + t] = ws[0] + ws[1] + ws[2] + ws[3] + bout[0];
}

// ---------------- launch ----------------
extern "C" void kernel_launch(void* const* d_in, const int* in_sizes, int n_in,
                              void* d_out, int out_size) {
    int wi = (n_in >= 8) ? 2 : 1;   // skip scalar `steps` input if present
    const float* tok  = (const float*)d_in[0];
    const float* Wih  = (const float*)d_in[wi];
    const float* Whh  = (const float*)d_in[wi + 1];
    const float* bih  = (const float*)d_in[wi + 2];
    const float* bhh  = (const float*)d_in[wi + 3];
    const float* Wout = (const float*)d_in[wi + 4];
    const float* bout = (const float*)d_in[wi + 5];
    float* out = (float*)d_out;

    cudaFuncSetAttribute(lstm_step, cudaFuncAttributeMaxDynamicSharedMemorySize, SMEM_REQ);

    prep_weights<<<32768, 256>>>(Wih, Whh);
    prep_misc<<<512, 256>>>(tok, bih, bhh);
    for (int t = 0; t < NSTEPS; t++)
        lstm_step<<<NTILE, 256, SMEM_REQ>>>(t);
    out_kernel<<<NSTEPS * BATCHN, 128>>>(Wout, bout, out);
}

// round 7
// speedup vs baseline: 1.9069x; 1.2589x over previous
#include <cuda_runtime.h>
#include <cuda_fp16.h>
#include <stdint.h>

// ---------------- problem constants ----------------
#define HID     2048
#define BATCHN  64
#define G4      8192
#define NSTEPS  30
#define NTILE   128           // M tiles of 64 gate-rows -> 128 CTAs
#define NKCH    32            // K chunks of 64 fp16 (128B rows, SW128)
#define WCH     8192          // bytes per W chunk tile (64 rows x 128B)
#define HCH     8192          // bytes per h chunk tile (64 batch x 128B)
#define STG     16384         // stage = W 8K + h 8K
#define NSTG    4
#define SMEM_REQ (NSTG*STG + 1024)

// ---------------- device scratch (static, no allocs) ----------------
__device__ __align__(1024) unsigned char g_wsum[NTILE*NKCH*WCH]; // 32MB fp16 (Wih+Whh)
__device__ __align__(1024) unsigned char g_whh [NTILE*NKCH*WCH]; // 32MB fp16 (Whh, step 0)
__device__ __align__(1024) unsigned char g_hA[NKCH*HCH];         // 256KB tiled fp16 h
__device__ __align__(1024) unsigned char g_hB[NKCH*HCH];
__device__ float g_c[BATCHN*HID];
__device__ float g_bias[G4];
__device__ float g_hist[NSTEPS*BATCHN*HID];

// ---------------- helpers ----------------
__device__ __forceinline__ uint32_t smem_u32(const void* p) {
    uint32_t a;
    asm("{ .reg .u64 t; cvta.to.shared.u64 t, %1; cvt.u32.u64 %0, t; }" : "=r"(a) : "l"(p));
    return a;
}
__device__ __forceinline__ uint32_t swz(uint32_t o) { return o ^ ((o >> 3) & 0x70); }

__device__ __forceinline__ void ldm4(uint32_t* r, uint32_t a) {
    asm volatile("ldmatrix.sync.aligned.m8n8.x4.shared.b16 {%0,%1,%2,%3}, [%4];"
                 : "=r"(r[0]), "=r"(r[1]), "=r"(r[2]), "=r"(r[3]) : "r"(a));
}
__device__ __forceinline__ void mma16816(float* d, const uint32_t* a, uint32_t b0, uint32_t b1) {
    asm volatile("mma.sync.aligned.m16n8k16.row.col.f32.f16.f16.f32 "
                 "{%0,%1,%2,%3}, {%4,%5,%6,%7}, {%8,%9}, {%0,%1,%2,%3};"
                 : "+f"(d[0]), "+f"(d[1]), "+f"(d[2]), "+f"(d[3])
                 : "r"(a[0]), "r"(a[1]), "r"(a[2]), "r"(a[3]), "r"(b0), "r"(b1));
}
__device__ __forceinline__ void cp16(uint32_t dst, const void* src) {
    asm volatile("cp.async.cg.shared.global [%0], [%1], 16;" :: "r"(dst), "l"(src) : "memory");
}
__device__ __forceinline__ float sigm(float x) {
    x = fminf(15.f, fmaxf(-15.f, x));
    return 1.f / (1.f + __expf(-x));
}
__device__ __forceinline__ float tanh_(float x) {
    x = fminf(8.f, fmaxf(-8.f, x));
    float e = __expf(-2.f * x);
    return (1.f - e) / (1.f + e);
}

// ---------------- prep: tiled + SW128-swizzled fp16 weights ----------------
// Tile t (0..127), row r (0..63): gate = r>>4, unit = r&15 -> orig row gate*HID + t*16 + unit.
__global__ void prep_weights(const float* __restrict__ Wih, const float* __restrict__ Whh) {
    int id  = blockIdx.x * 256 + threadIdx.x;     // 8,388,608 (one half2 each)
    int cp  = id & 31;
    int row = (id >> 5) & 63;
    int kc  = (id >> 11) & 31;
    int t   = id >> 16;
    int gate = row >> 4, u = row & 15;
    long orow = (long)gate * HID + t * 16 + u;
    int  ocol = kc * 64 + cp * 2;
    float2 wi = *(const float2*)(Wih + orow * HID + ocol);
    float2 wh = *(const float2*)(Whh + orow * HID + ocol);
    uint32_t toff = (uint32_t)(t * NKCH + kc) * WCH + swz((uint32_t)(row * 128 + cp * 4));
    *(__half2*)(g_wsum + toff) =
        __halves2half2(__float2half_rn(wi.x + wh.x), __float2half_rn(wi.y + wh.y));
    *(__half2*)(g_whh + toff) =
        __halves2half2(__float2half_rn(wh.x), __float2half_rn(wh.y));
}

// zero c, fused bias, tiled fp16 h0 into buffer A
__global__ void prep_misc(const float* __restrict__ tok,
                          const float* __restrict__ bih, const float* __restrict__ bhh) {
    int id = blockIdx.x * 256 + threadIdx.x;      // 131072
    float h0 = tok[id];
    g_c[id] = 0.0f;
    int b = id >> 11, hid = id & 2047;
    int kc = hid >> 6, cc = hid & 63;
    uint32_t off = (uint32_t)kc * HCH + swz((uint32_t)(b * 128 + cc * 2));
    *(__half*)(g_hA + off) = __float2half_rn(h0);
    if (id < G4) g_bias[id] = bih[id] + bhh[id];
}

// ---------------- one LSTM step ----------------
// 512 threads, warp grid 2M x 2N x 4K:
//   kw = wid&3 owns k16 slice ks=kw of every chunk; warp tile m32 x n32.
#define SMX(g, b, u) smx[((g) * 64 + (b)) * 17 + (u)]

__global__ void __launch_bounds__(512, 1) lstm_step(int step) {
    extern __shared__ unsigned char smraw[];
    uint32_t sbr  = smem_u32(smraw);
    uint32_t base = (sbr + 1023) & ~1023u;
    float* smx = (float*)(smraw + (base - sbr));   // epilogue scratch, overlaps stage 0-1

    int tid = threadIdx.x;
    int lane = tid & 31, wid = tid >> 5;
    int kw     = wid & 3;
    int warp_m = (wid >> 2) & 1;
    int warp_n = wid >> 3;
    int blk = blockIdx.x;

    const unsigned char* wsrc = ((step ? g_wsum : g_whh) + (size_t)blk * NKCH * WCH);
    const unsigned char* hsrc = (step & 1) ? g_hB : g_hA;
    unsigned char*       hout = (step & 1) ? g_hA : g_hB;

    // ldmatrix lane address components (k16 slice at byte offset kw*32)
    uint32_t kof    = (uint32_t)kw * 32;
    uint32_t a_colb = (uint32_t)((lane >> 4) << 4);
    uint32_t a_r0   = (uint32_t)(warp_m * 32 + (lane & 15));
    uint32_t b_row  = (uint32_t)(warp_n * 32 + (lane & 7) + ((lane >> 4) << 3));
    uint32_t b_colb = (uint32_t)(((lane >> 3) & 1) << 4);

    float acc[2][16];
    #pragma unroll
    for (int i = 0; i < 2; i++)
        #pragma unroll
        for (int j = 0; j < 16; j++) acc[i][j] = 0.f;

    // prefetch chunks 0..2 (512 threads: one 16B per array each)
    #pragma unroll
    for (int c = 0; c < 3; c++) {
        uint32_t sb = base + (uint32_t)c * STG;
        int o = tid * 16;
        cp16(sb + o,        wsrc + (size_t)c * WCH + o);
        cp16(sb + 8192 + o, hsrc + (size_t)c * HCH + o);
        asm volatile("cp.async.commit_group;" ::: "memory");
    }

    for (int kc = 0; kc < NKCH; kc++) {
        if (kc <= 29)      asm volatile("cp.async.wait_group 2;" ::: "memory");
        else if (kc == 30) asm volatile("cp.async.wait_group 1;" ::: "memory");
        else               asm volatile("cp.async.wait_group 0;" ::: "memory");
        __syncthreads();

        int nc = kc + 3;
        if (nc < NKCH) {
            uint32_t sb = base + (uint32_t)(nc & 3) * STG;
            int o = tid * 16;
            cp16(sb + o,        wsrc + (size_t)nc * WCH + o);
            cp16(sb + 8192 + o, hsrc + (size_t)nc * HCH + o);
            asm volatile("cp.async.commit_group;" ::: "memory");
        }

        uint32_t sw = base + (uint32_t)(kc & 3) * STG;
        uint32_t sh = sw + 8192;
        uint32_t a0[4], a1[4], b0[4], b1[4];
        ldm4(a0, sw + swz(a_r0 * 128 + kof + a_colb));
        ldm4(a1, sw + swz((a_r0 + 16) * 128 + kof + a_colb));
        ldm4(b0, sh + swz(b_row * 128 + kof + b_colb));
        ldm4(b1, sh + swz((b_row + 16) * 128 + kof + b_colb));
        mma16816(acc[0] + 0,  a0, b0[0], b0[1]);
        mma16816(acc[0] + 4,  a0, b0[2], b0[3]);
        mma16816(acc[0] + 8,  a0, b1[0], b1[1]);
        mma16816(acc[0] + 12, a0, b1[2], b1[3]);
        mma16816(acc[1] + 0,  a1, b0[0], b0[1]);
        mma16816(acc[1] + 4,  a1, b0[2], b0[3]);
        mma16816(acc[1] + 8,  a1, b1[0], b1[1]);
        mma16816(acc[1] + 12, a1, b1[2], b1[3]);
    }
    __syncthreads();

    // ---- K-group reduction into smx[gate][batch][unit] (4 sequential rounds) ----
    #pragma unroll
    for (int r = 0; r < 4; r++) {
        if (kw == r) {
            #pragma unroll
            for (int mt = 0; mt < 2; mt++) {
                int gate = warp_m * 2 + mt;
                #pragma unroll
                for (int g = 0; g < 4; g++) {
                    int n0 = warp_n * 32 + 8 * g + 2 * (lane & 3);
                    int u0 = lane >> 2;
                    if (r == 0) {
                        SMX(gate, n0,     u0    ) = acc[mt][4 * g + 0];
                        SMX(gate, n0 + 1, u0    ) = acc[mt][4 * g + 1];
                        SMX(gate, n0,     u0 + 8) = acc[mt][4 * g + 2];
                        SMX(gate, n0 + 1, u0 + 8) = acc[mt][4 * g + 3];
                    } else {
                        SMX(gate, n0,     u0    ) += acc[mt][4 * g + 0];
                        SMX(gate, n0 + 1, u0    ) += acc[mt][4 * g + 1];
                        SMX(gate, n0,     u0 + 8) += acc[mt][4 * g + 2];
                        SMX(gate, n0 + 1, u0 + 8) += acc[mt][4 * g + 3];
                    }
                }
            }
        }
        __syncthreads();
    }

    // ---- fused LSTM cell: 16 units x 64 batch per CTA ----
    int kcb = blk >> 2;
    #pragma unroll
    for (int k = 0; k < 2; k++) {
        int p = k * 512 + tid;          // (unit, batch)
        int u = p & 15, b = p >> 4;
        int hid = blk * 16 + u;
        float xi = SMX(0, b, u) + g_bias[hid];
        float xf = SMX(1, b, u) + g_bias[2048 + hid];
        float xg = SMX(2, b, u) + g_bias[4096 + hid];
        float xo = SMX(3, b, u) + g_bias[6144 + hid];
        float ii = sigm(xi), ff = sigm(xf), gg = tanh_(xg), oo = sigm(xo);
        int ci = b * HID + hid;
        float c = ff * g_c[ci] + ii * gg;
        g_c[ci] = c;
        float h = oo * tanh_(c);
        g_hist[((size_t)step * BATCHN + b) * HID + hid] = h;
        uint32_t off = (uint32_t)kcb * HCH +
                       swz((uint32_t)(b * 128 + ((blk & 3) * 16 + u) * 2));
        *(__half*)(hout + off) = __float2half_rn(h);
    }
}

// ---------------- output projection: y[b,t] = hist[t,b,:] . W_out + b_out ----------------
__global__ void out_kernel(const float* __restrict__ Wout, const float* __restrict__ bout,
                           float* __restrict__ out) {
    int t = blockIdx.x / BATCHN;
    int b = blockIdx.x % BATCHN;
    const float4* h = (const float4*)(g_hist + ((size_t)t * BATCHN + b) * HID);
    const float4* w = (const float4*)Wout;
    float acc = 0.f;
    #pragma unroll
    for (int it = 0; it < 4; it++) {
        int k = it * 128 + threadIdx.x;
        float4 hv = h[k], wv = w[k];
        acc += hv.x * wv.x + hv.y * wv.y + hv.z * wv.z + hv.w * wv.w;
    }
    #pragma unroll
    for (int o = 16; o; o >>= 1) acc += __shfl_xor_sync(0xFFFFFFFFu, acc, o);
    __shared__ float ws[4];
    if ((threadIdx.x & 31) == 0) ws[threadIdx.x >> 5] = acc;
    __syncthreads();
    if (threadIdx.x == 0)
        out[b * NSTEPS + t] = ws[0] + ws[1] + ws[2] + ws[3] + bout[0];
}

// ---------------- launch ----------------
extern "C" void kernel_launch(void* const* d_in, const int* in_sizes, int n_in,
                              void* d_out, int out_size) {
    int wi = (n_in >= 8) ? 2 : 1;   // skip scalar `steps` input if present
    const float* tok  = (const float*)d_in[0];
    const float* Wih  = (const float*)d_in[wi];
    const float* Whh  = (const float*)d_in[wi + 1];
    const float* bih  = (const float*)d_in[wi + 2];
    const float* bhh  = (const float*)d_in[wi + 3];
    const float* Wout = (const float*)d_in[wi + 4];
    const float* bout = (const float*)d_in[wi + 5];
    float* out = (float*)d_out;

    cudaFuncSetAttribute(lstm_step, cudaFuncAttributeMaxDynamicSharedMemorySize, SMEM_REQ);

    prep_weights<<<32768, 256>>>(Wih, Whh);
    prep_misc<<<512, 256>>>(tok, bih, bhh);
    for (int t = 0; t < NSTEPS; t++)
        lstm_step<<<NTILE, 512, SMEM_REQ>>>(t);
    out_kernel<<<NSTEPS * BATCHN, 128>>>(Wout, bout, out);
}

// round 8
// speedup vs baseline: 1.9337x; 1.0140x over previous
#include <cuda_runtime.h>
#include <cuda_fp16.h>
#include <stdint.h>

// ---------------- problem constants ----------------
#define HID     2048
#define BATCHN  64
#define G4      8192
#define NSTEPS  30
#define NTILE   128           // M tiles of 64 gate-rows -> 128 CTAs
#define NKCH    32            // K chunks of 64 fp16 (128B rows, SW128)
#define WCH     8192          // bytes per W chunk tile (64 rows x 128B)
#define HCH     8192          // bytes per h chunk tile (64 batch x 128B)
#define NITER   16            // 2 chunks per iteration
#define STG     32768         // stage = 2 x (W 8K + h 8K)
#define NSTG    3
#define SMEM_REQ (NSTG*STG + 1024)

// ---------------- device scratch (static, no allocs) ----------------
__device__ __align__(1024) unsigned char g_wsum[NTILE*NKCH*WCH]; // 32MB fp16 (Wih+Whh)
__device__ __align__(1024) unsigned char g_whh [NTILE*NKCH*WCH]; // 32MB fp16 (Whh, step 0)
__device__ __align__(1024) unsigned char g_hA[NKCH*HCH];         // 256KB tiled fp16 h
__device__ __align__(1024) unsigned char g_hB[NKCH*HCH];
__device__ float g_c[BATCHN*HID];
__device__ float g_bias[G4];
__device__ float g_hist[NSTEPS*BATCHN*HID];

// ---------------- helpers ----------------
__device__ __forceinline__ uint32_t smem_u32(const void* p) {
    uint32_t a;
    asm("{ .reg .u64 t; cvta.to.shared.u64 t, %1; cvt.u32.u64 %0, t; }" : "=r"(a) : "l"(p));
    return a;
}
__device__ __forceinline__ uint32_t swz(uint32_t o) { return o ^ ((o >> 3) & 0x70); }

__device__ __forceinline__ void ldm4(uint32_t* r, uint32_t a) {
    asm volatile("ldmatrix.sync.aligned.m8n8.x4.shared.b16 {%0,%1,%2,%3}, [%4];"
                 : "=r"(r[0]), "=r"(r[1]), "=r"(r[2]), "=r"(r[3]) : "r"(a));
}
__device__ __forceinline__ void mma16816(float* d, const uint32_t* a, uint32_t b0, uint32_t b1) {
    asm volatile("mma.sync.aligned.m16n8k16.row.col.f32.f16.f16.f32 "
                 "{%0,%1,%2,%3}, {%4,%5,%6,%7}, {%8,%9}, {%0,%1,%2,%3};"
                 : "+f"(d[0]), "+f"(d[1]), "+f"(d[2]), "+f"(d[3])
                 : "r"(a[0]), "r"(a[1]), "r"(a[2]), "r"(a[3]), "r"(b0), "r"(b1));
}
__device__ __forceinline__ void cp16(uint32_t dst, const void* src) {
    asm volatile("cp.async.cg.shared.global [%0], [%1], 16;" :: "r"(dst), "l"(src) : "memory");
}
__device__ __forceinline__ float sigm(float x) {
    x = fminf(15.f, fmaxf(-15.f, x));
    return 1.f / (1.f + __expf(-x));
}
__device__ __forceinline__ float tanh_(float x) {
    x = fminf(8.f, fmaxf(-8.f, x));
    float e = __expf(-2.f * x);
    return (1.f - e) / (1.f + e);
}

// ---------------- prep: tiled + SW128-swizzled fp16 weights ----------------
// Tile t (0..127), row r (0..63): gate = r>>4, unit = r&15 -> orig row gate*HID + t*16 + unit.
__global__ void prep_weights(const float* __restrict__ Wih, const float* __restrict__ Whh) {
    int id  = blockIdx.x * 256 + threadIdx.x;     // 8,388,608 (one half2 each)
    int cp  = id & 31;
    int row = (id >> 5) & 63;
    int kc  = (id >> 11) & 31;
    int t   = id >> 16;
    int gate = row >> 4, u = row & 15;
    long orow = (long)gate * HID + t * 16 + u;
    int  ocol = kc * 64 + cp * 2;
    float2 wi = *(const float2*)(Wih + orow * HID + ocol);
    float2 wh = *(const float2*)(Whh + orow * HID + ocol);
    uint32_t toff = (uint32_t)(t * NKCH + kc) * WCH + swz((uint32_t)(row * 128 + cp * 4));
    *(__half2*)(g_wsum + toff) =
        __halves2half2(__float2half_rn(wi.x + wh.x), __float2half_rn(wi.y + wh.y));
    *(__half2*)(g_whh + toff) =
        __halves2half2(__float2half_rn(wh.x), __float2half_rn(wh.y));
}

// zero c, fused bias, tiled fp16 h0 into buffer A
__global__ void prep_misc(const float* __restrict__ tok,
                          const float* __restrict__ bih, const float* __restrict__ bhh) {
    int id = blockIdx.x * 256 + threadIdx.x;      // 131072
    float h0 = tok[id];
    g_c[id] = 0.0f;
    int b = id >> 11, hid = id & 2047;
    int kc = hid >> 6, cc = hid & 63;
    uint32_t off = (uint32_t)kc * HCH + swz((uint32_t)(b * 128 + cc * 2));
    *(__half*)(g_hA + off) = __float2half_rn(h0);
    if (id < G4) g_bias[id] = bih[id] + bhh[id];
}

// ---------------- one LSTM step ----------------
// 512 threads, warp grid 2M x 2N x 4K; 2 chunks per pipeline stage.
#define SMX(g, b, u) smx[((g) * 64 + (b)) * 17 + (u)]

__global__ void __launch_bounds__(512, 1) lstm_step(int step) {
    extern __shared__ unsigned char smraw[];
    uint32_t sbr  = smem_u32(smraw);
    uint32_t base = (sbr + 1023) & ~1023u;
    float* smx = (float*)(smraw + (base - sbr));   // epilogue scratch, overlaps stage 0

    int tid = threadIdx.x;
    int lane = tid & 31, wid = tid >> 5;
    int kw     = wid & 3;
    int warp_m = (wid >> 2) & 1;
    int warp_n = wid >> 3;
    int blk = blockIdx.x;

    const unsigned char* wsrc = ((step ? g_wsum : g_whh) + (size_t)blk * NKCH * WCH);
    const unsigned char* hsrc = (step & 1) ? g_hB : g_hA;
    unsigned char*       hout = (step & 1) ? g_hA : g_hB;

    // ldmatrix lane address components (k16 slice at byte offset kw*32)
    uint32_t kof    = (uint32_t)kw * 32;
    uint32_t a_colb = (uint32_t)((lane >> 4) << 4);
    uint32_t a_r0   = (uint32_t)(warp_m * 32 + (lane & 15));
    uint32_t b_row  = (uint32_t)(warp_n * 32 + (lane & 7) + ((lane >> 4) << 3));
    uint32_t b_colb = (uint32_t)(((lane >> 3) & 1) << 4);

    float acc[2][16];
    #pragma unroll
    for (int i = 0; i < 2; i++)
        #pragma unroll
        for (int j = 0; j < 16; j++) acc[i][j] = 0.f;

    // prefetch stages 0,1 (chunks 0..3); per stage each thread copies 4x16B
    #pragma unroll
    for (int s = 0; s < 2; s++) {
        uint32_t sb = base + (uint32_t)s * STG;
        size_t gw = (size_t)(2 * s) * WCH;
        size_t gh = (size_t)(2 * s) * HCH;
        int o = tid * 16;
        cp16(sb + o,         wsrc + gw + o);
        cp16(sb + 8192 + o,  hsrc + gh + o);
        cp16(sb + 16384 + o, wsrc + gw + WCH + o);
        cp16(sb + 24576 + o, hsrc + gh + HCH + o);
        asm volatile("cp.async.commit_group;" ::: "memory");
    }

    for (int kp = 0; kp < NITER; kp++) {
        if (kp < NITER - 1) asm volatile("cp.async.wait_group 1;" ::: "memory");
        else                asm volatile("cp.async.wait_group 0;" ::: "memory");
        __syncthreads();

        int np = kp + 2;
        if (np < NITER) {
            uint32_t sb = base + (uint32_t)(np % NSTG) * STG;
            size_t gw = (size_t)(2 * np) * WCH;
            size_t gh = (size_t)(2 * np) * HCH;
            int o = tid * 16;
            cp16(sb + o,         wsrc + gw + o);
            cp16(sb + 8192 + o,  hsrc + gh + o);
            cp16(sb + 16384 + o, wsrc + gw + WCH + o);
            cp16(sb + 24576 + o, hsrc + gh + HCH + o);
            asm volatile("cp.async.commit_group;" ::: "memory");
        }

        uint32_t sb = base + (uint32_t)(kp % NSTG) * STG;
        #pragma unroll
        for (int c = 0; c < 2; c++) {
            uint32_t sw = sb + (uint32_t)c * 16384;
            uint32_t sh = sw + 8192;
            uint32_t a0[4], a1[4], b0[4], b1[4];
            ldm4(a0, sw + swz(a_r0 * 128 + kof + a_colb));
            ldm4(a1, sw + swz((a_r0 + 16) * 128 + kof + a_colb));
            ldm4(b0, sh + swz(b_row * 128 + kof + b_colb));
            ldm4(b1, sh + swz((b_row + 16) * 128 + kof + b_colb));
            mma16816(acc[0] + 0,  a0, b0[0], b0[1]);
            mma16816(acc[0] + 4,  a0, b0[2], b0[3]);
            mma16816(acc[0] + 8,  a0, b1[0], b1[1]);
            mma16816(acc[0] + 12, a0, b1[2], b1[3]);
            mma16816(acc[1] + 0,  a1, b0[0], b0[1]);
            mma16816(acc[1] + 4,  a1, b0[2], b0[3]);
            mma16816(acc[1] + 8,  a1, b1[0], b1[1]);
            mma16816(acc[1] + 12, a1, b1[2], b1[3]);
        }
    }
    __syncthreads();

    // ---- K-group reduction into smx[gate][batch][unit] (4 sequential rounds) ----
    #pragma unroll
    for (int r = 0; r < 4; r++) {
        if (kw == r) {
            #pragma unroll
            for (int mt = 0; mt < 2; mt++) {
                int gate = warp_m * 2 + mt;
                #pragma unroll
                for (int g = 0; g < 4; g++) {
                    int n0 = warp_n * 32 + 8 * g + 2 * (lane & 3);
                    int u0 = lane >> 2;
                    if (r == 0) {
                        SMX(gate, n0,     u0    ) = acc[mt][4 * g + 0];
                        SMX(gate, n0 + 1, u0    ) = acc[mt][4 * g + 1];
                        SMX(gate, n0,     u0 + 8) = acc[mt][4 * g + 2];
                        SMX(gate, n0 + 1, u0 + 8) = acc[mt][4 * g + 3];
                    } else {
                        SMX(gate, n0,     u0    ) += acc[mt][4 * g + 0];
                        SMX(gate, n0 + 1, u0    ) += acc[mt][4 * g + 1];
                        SMX(gate, n0,     u0 + 8) += acc[mt][4 * g + 2];
                        SMX(gate, n0 + 1, u0 + 8) += acc[mt][4 * g + 3];
                    }
                }
            }
        }
        __syncthreads();
    }

    // ---- fused LSTM cell: 16 units x 64 batch per CTA ----
    int kcb = blk >> 2;
    #pragma unroll
    for (int k = 0; k < 2; k++) {
        int p = k * 512 + tid;          // (unit, batch)
        int u = p & 15, b = p >> 4;
        int hid = blk * 16 + u;
        float xi = SMX(0, b, u) + g_bias[hid];
        float xf = SMX(1, b, u) + g_bias[2048 + hid];
        float xg = SMX(2, b, u) + g_bias[4096 + hid];
        float xo = SMX(3, b, u) + g_bias[6144 + hid];
        float ii = sigm(xi), ff = sigm(xf), gg = tanh_(xg), oo = sigm(xo);
        int ci = b * HID + hid;
        float c = ff * g_c[ci] + ii * gg;
        g_c[ci] = c;
        float h = oo * tanh_(c);
        g_hist[((size_t)step * BATCHN + b) * HID + hid] = h;
        uint32_t off = (uint32_t)kcb * HCH +
                       swz((uint32_t)(b * 128 + ((blk & 3) * 16 + u) * 2));
        *(__half*)(hout + off) = __float2half_rn(h);
    }
}

// ---------------- output projection: y[b,t] = hist[t,b,:] . W_out + b_out ----------------
__global__ void out_kernel(const float* __restrict__ Wout, const float* __restrict__ bout,
                           float* __restrict__ out) {
    int t = blockIdx.x / BATCHN;
    int b = blockIdx.x % BATCHN;
    const float4* h = (const float4*)(g_hist + ((size_t)t * BATCHN + b) * HID);
    const float4* w = (const float4*)Wout;
    float acc = 0.f;
    #pragma unroll
    for (int it = 0; it < 4; it++) {
        int k = it * 128 + threadIdx.x;
        float4 hv = h[k], wv = w[k];
        acc += hv.x * wv.x + hv.y * wv.y + hv.z * wv.z + hv.w * wv.w;
    }
    #pragma unroll
    for (int o = 16; o; o >>= 1) acc += __shfl_xor_sync(0xFFFFFFFFu, acc, o);
    __shared__ float ws[4];
    if ((threadIdx.x & 31) == 0) ws[threadIdx.x >> 5] = acc;
    __syncthreads();
    if (threadIdx.x == 0)
        out[b * NSTEPS + t] = ws[0] + ws[1] + ws[2] + ws[3] + bout[0];
}

// ---------------- launch ----------------
extern "C" void kernel_launch(void* const* d_in, const int* in_sizes, int n_in,
                              void* d_out, int out_size) {
    int wi = (n_in >= 8) ? 2 : 1;   // skip scalar `steps` input if present
    const float* tok  = (const float*)d_in[0];
    const float* Wih  = (const float*)d_in[wi];
    const float* Whh  = (const float*)d_in[wi + 1];
    const float* bih  = (const float*)d_in[wi + 2];
    const float* bhh  = (const float*)d_in[wi + 3];
    const float* Wout = (const float*)d_in[wi + 4];
    const float* bout = (const float*)d_in[wi + 5];
    float* out = (float*)d_out;

    cudaFuncSetAttribute(lstm_step, cudaFuncAttributeMaxDynamicSharedMemorySize, SMEM_REQ);

    prep_weights<<<32768, 256>>>(Wih, Whh);
    prep_misc<<<512, 256>>>(tok, bih, bhh);
    for (int t = 0; t < NSTEPS; t++)
        lstm_step<<<NTILE, 512, SMEM_REQ>>>(t);
    out_kernel<<<NSTEPS * BATCHN, 128>>>(Wout, bout, out);
}

// round 9
// speedup vs baseline: 1.9556x; 1.0113x over previous
#include <cuda_runtime.h>
#include <cuda_fp16.h>
#include <stdint.h>

// ---------------- problem constants ----------------
#define HID     2048
#define BATCHN  64
#define G4      8192
#define NSTEPS  30
#define NTILE   128           // M tiles of 64 gate-rows -> 128 CTAs
#define NKCH    32            // K chunks of 64 fp16 (128B rows, SW128)
#define WCH     8192          // bytes per W chunk tile (64 rows x 128B)
#define HCH     8192          // bytes per h chunk tile (64 batch x 128B)
#define NITER   16            // 2 chunks per iteration
#define STG     32768         // stage = 2 x (W 8K + h 8K)
#define NSTG    4
#define SMEM_REQ (NSTG*STG + 1024)

// ---------------- device scratch (static, no allocs) ----------------
__device__ __align__(1024) unsigned char g_wsum[NTILE*NKCH*WCH]; // 32MB fp16 (Wih+Whh)
__device__ __align__(1024) unsigned char g_whh [NTILE*NKCH*WCH]; // 32MB fp16 (Whh, step 0)
__device__ __align__(1024) unsigned char g_hA[NKCH*HCH];         // 256KB tiled fp16 h
__device__ __align__(1024) unsigned char g_hB[NKCH*HCH];
__device__ float g_c[BATCHN*HID];
__device__ float g_bias[G4];
__device__ float g_hist[NSTEPS*BATCHN*HID];

// ---------------- helpers ----------------
__device__ __forceinline__ uint32_t smem_u32(const void* p) {
    uint32_t a;
    asm("{ .reg .u64 t; cvta.to.shared.u64 t, %1; cvt.u32.u64 %0, t; }" : "=r"(a) : "l"(p));
    return a;
}
__device__ __forceinline__ uint32_t swz(uint32_t o) { return o ^ ((o >> 3) & 0x70); }

__device__ __forceinline__ void ldm4(uint32_t* r, uint32_t a) {
    asm volatile("ldmatrix.sync.aligned.m8n8.x4.shared.b16 {%0,%1,%2,%3}, [%4];"
                 : "=r"(r[0]), "=r"(r[1]), "=r"(r[2]), "=r"(r[3]) : "r"(a));
}
__device__ __forceinline__ void mma16816(float* d, const uint32_t* a, uint32_t b0, uint32_t b1) {
    asm volatile("mma.sync.aligned.m16n8k16.row.col.f32.f16.f16.f32 "
                 "{%0,%1,%2,%3}, {%4,%5,%6,%7}, {%8,%9}, {%0,%1,%2,%3};"
                 : "+f"(d[0]), "+f"(d[1]), "+f"(d[2]), "+f"(d[3])
                 : "r"(a[0]), "r"(a[1]), "r"(a[2]), "r"(a[3]), "r"(b0), "r"(b1));
}
__device__ __forceinline__ void cp16(uint32_t dst, const void* src) {
    asm volatile("cp.async.cg.shared.global [%0], [%1], 16;" :: "r"(dst), "l"(src) : "memory");
}
__device__ __forceinline__ float sigm(float x) {
    x = fminf(15.f, fmaxf(-15.f, x));
    return 1.f / (1.f + __expf(-x));
}
__device__ __forceinline__ float tanh_(float x) {
    x = fminf(8.f, fmaxf(-8.f, x));
    float e = __expf(-2.f * x);
    return (1.f - e) / (1.f + e);
}

// ---------------- prep: tiled + SW128-swizzled fp16 weights ----------------
// Tile t (0..127), row r (0..63): gate = r>>4, unit = r&15 -> orig row gate*HID + t*16 + unit.
__global__ void prep_weights(const float* __restrict__ Wih, const float* __restrict__ Whh) {
    int id  = blockIdx.x * 256 + threadIdx.x;     // 8,388,608 (one half2 each)
    int cp  = id & 31;
    int row = (id >> 5) & 63;
    int kc  = (id >> 11) & 31;
    int t   = id >> 16;
    int gate = row >> 4, u = row & 15;
    long orow = (long)gate * HID + t * 16 + u;
    int  ocol = kc * 64 + cp * 2;
    float2 wi = *(const float2*)(Wih + orow * HID + ocol);
    float2 wh = *(const float2*)(Whh + orow * HID + ocol);
    uint32_t toff = (uint32_t)(t * NKCH + kc) * WCH + swz((uint32_t)(row * 128 + cp * 4));
    *(__half2*)(g_wsum + toff) =
        __halves2half2(__float2half_rn(wi.x + wh.x), __float2half_rn(wi.y + wh.y));
    *(__half2*)(g_whh + toff) =
        __halves2half2(__float2half_rn(wh.x), __float2half_rn(wh.y));
}

// zero c, fused bias, tiled fp16 h0 into buffer A
__global__ void prep_misc(const float* __restrict__ tok,
                          const float* __restrict__ bih, const float* __restrict__ bhh) {
    int id = blockIdx.x * 256 + threadIdx.x;      // 131072
    float h0 = tok[id];
    g_c[id] = 0.0f;
    int b = id >> 11, hid = id & 2047;
    int kc = hid >> 6, cc = hid & 63;
    uint32_t off = (uint32_t)kc * HCH + swz((uint32_t)(b * 128 + cc * 2));
    *(__half*)(g_hA + off) = __float2half_rn(h0);
    if (id < G4) g_bias[id] = bih[id] + bhh[id];
}

// ---------------- one LSTM step ----------------
// 512 threads, warp grid 2M x 2N x 4K; 2 chunks per iteration, 4 stages in flight.
#define SMX(g, b, u) smx[((g) * 64 + (b)) * 17 + (u)]

__global__ void __launch_bounds__(512, 1) lstm_step(int step) {
    extern __shared__ unsigned char smraw[];
    uint32_t sbr  = smem_u32(smraw);
    uint32_t base = (sbr + 1023) & ~1023u;
    float* smx = (float*)(smraw + (base - sbr));   // epilogue scratch, overlaps stage 0

    int tid = threadIdx.x;
    int lane = tid & 31, wid = tid >> 5;
    int kw     = wid & 3;
    int warp_m = (wid >> 2) & 1;
    int warp_n = wid >> 3;
    int blk = blockIdx.x;

    const unsigned char* wsrc = ((step ? g_wsum : g_whh) + (size_t)blk * NKCH * WCH);
    const unsigned char* hsrc = (step & 1) ? g_hB : g_hA;
    unsigned char*       hout = (step & 1) ? g_hA : g_hB;

    // ldmatrix lane address components (k16 slice at byte offset kw*32)
    uint32_t kof    = (uint32_t)kw * 32;
    uint32_t a_colb = (uint32_t)((lane >> 4) << 4);
    uint32_t a_r0   = (uint32_t)(warp_m * 32 + (lane & 15));
    uint32_t b_row  = (uint32_t)(warp_n * 32 + (lane & 7) + ((lane >> 4) << 3));
    uint32_t b_colb = (uint32_t)(((lane >> 3) & 1) << 4);

    float acc[2][16];
    #pragma unroll
    for (int i = 0; i < 2; i++)
        #pragma unroll
        for (int j = 0; j < 16; j++) acc[i][j] = 0.f;

    // prefetch stages 0..2 (chunks 0..5)
    #pragma unroll
    for (int s = 0; s < 3; s++) {
        uint32_t sb = base + (uint32_t)s * STG;
        size_t gw = (size_t)(2 * s) * WCH;
        size_t gh = (size_t)(2 * s) * HCH;
        int o = tid * 16;
        cp16(sb + o,         wsrc + gw + o);
        cp16(sb + 8192 + o,  hsrc + gh + o);
        cp16(sb + 16384 + o, wsrc + gw + WCH + o);
        cp16(sb + 24576 + o, hsrc + gh + HCH + o);
        asm volatile("cp.async.commit_group;" ::: "memory");
    }

    for (int kp = 0; kp < NITER; kp++) {
        // stage kp must be complete; keep up to 2 newer stages in flight
        if (kp < NITER - 2)      asm volatile("cp.async.wait_group 2;" ::: "memory");
        else if (kp == NITER - 2) asm volatile("cp.async.wait_group 1;" ::: "memory");
        else                      asm volatile("cp.async.wait_group 0;" ::: "memory");
        __syncthreads();

        // refill stage (kp+3)%4 == (kp-1)%4, freed by the barrier above
        int np = kp + 3;
        if (np < NITER) {
            uint32_t sb = base + (uint32_t)(np & 3) * STG;
            size_t gw = (size_t)(2 * np) * WCH;
            size_t gh = (size_t)(2 * np) * HCH;
            int o = tid * 16;
            cp16(sb + o,         wsrc + gw + o);
            cp16(sb + 8192 + o,  hsrc + gh + o);
            cp16(sb + 16384 + o, wsrc + gw + WCH + o);
            cp16(sb + 24576 + o, hsrc + gh + HCH + o);
            asm volatile("cp.async.commit_group;" ::: "memory");
        }

        uint32_t sb = base + (uint32_t)(kp & 3) * STG;

        // front-load all fragments for both chunks, then MMA burst
        uint32_t fa0[2][4], fa1[2][4], fb0[2][4], fb1[2][4];
        #pragma unroll
        for (int c = 0; c < 2; c++) {
            uint32_t sw = sb + (uint32_t)c * 16384;
            uint32_t sh = sw + 8192;
            ldm4(fa0[c], sw + swz(a_r0 * 128 + kof + a_colb));
            ldm4(fa1[c], sw + swz((a_r0 + 16) * 128 + kof + a_colb));
            ldm4(fb0[c], sh + swz(b_row * 128 + kof + b_colb));
            ldm4(fb1[c], sh + swz((b_row + 16) * 128 + kof + b_colb));
        }
        #pragma unroll
        for (int c = 0; c < 2; c++) {
            mma16816(acc[0] + 0,  fa0[c], fb0[c][0], fb0[c][1]);
            mma16816(acc[0] + 4,  fa0[c], fb0[c][2], fb0[c][3]);
            mma16816(acc[0] + 8,  fa0[c], fb1[c][0], fb1[c][1]);
            mma16816(acc[0] + 12, fa0[c], fb1[c][2], fb1[c][3]);
            mma16816(acc[1] + 0,  fa1[c], fb0[c][0], fb0[c][1]);
            mma16816(acc[1] + 4,  fa1[c], fb0[c][2], fb0[c][3]);
            mma16816(acc[1] + 8,  fa1[c], fb1[c][0], fb1[c][1]);
            mma16816(acc[1] + 12, fa1[c], fb1[c][2], fb1[c][3]);
        }
    }
    __syncthreads();

    // ---- K-group reduction into smx[gate][batch][unit] (4 sequential rounds) ----
    #pragma unroll
    for (int r = 0; r < 4; r++) {
        if (kw == r) {
            #pragma unroll
            for (int mt = 0; mt < 2; mt++) {
                int gate = warp_m * 2 + mt;
                #pragma unroll
                for (int g = 0; g < 4; g++) {
                    int n0 = warp_n * 32 + 8 * g + 2 * (lane & 3);
                    int u0 = lane >> 2;
                    if (r == 0) {
                        SMX(gate, n0,     u0    ) = acc[mt][4 * g + 0];
                        SMX(gate, n0 + 1, u0    ) = acc[mt][4 * g + 1];
                        SMX(gate, n0,     u0 + 8) = acc[mt][4 * g + 2];
                        SMX(gate, n0 + 1, u0 + 8) = acc[mt][4 * g + 3];
                    } else {
                        SMX(gate, n0,     u0    ) += acc[mt][4 * g + 0];
                        SMX(gate, n0 + 1, u0    ) += acc[mt][4 * g + 1];
                        SMX(gate, n0,     u0 + 8) += acc[mt][4 * g + 2];
                        SMX(gate, n0 + 1, u0 + 8) += acc[mt][4 * g + 3];
                    }
                }
            }
        }
        __syncthreads();
    }

    // ---- fused LSTM cell: 16 units x 64 batch per CTA ----
    int kcb = blk >> 2;
    #pragma unroll
    for (int k = 0; k < 2; k++) {
        int p = k * 512 + tid;          // (unit, batch)
        int u = p & 15, b = p >> 4;
        int hid = blk * 16 + u;
        float xi = SMX(0, b, u) + g_bias[hid];
        float xf = SMX(1, b, u) + g_bias[2048 + hid];
        float xg = SMX(2, b, u) + g_bias[4096 + hid];
        float xo = SMX(3, b, u) + g_bias[6144 + hid];
        float ii = sigm(xi), ff = sigm(xf), gg = tanh_(xg), oo = sigm(xo);
        int ci = b * HID + hid;
        float c = ff * g_c[ci] + ii * gg;
        g_c[ci] = c;
        float h = oo * tanh_(c);
        uint32_t off = (uint32_t)kcb * HCH +
                       swz((uint32_t)(b * 128 + ((blk & 3) * 16 + u) * 2));
        *(__half*)(hout + off) = __float2half_rn(h);
        g_hist[((size_t)step * BATCHN + b) * HID + hid] = h;
    }
}

// ---------------- output projection: y[b,t] = hist[t,b,:] . W_out + b_out ----------------
__global__ void out_kernel(const float* __restrict__ Wout, const float* __restrict__ bout,
                           float* __restrict__ out) {
    int t = blockIdx.x / BATCHN;
    int b = blockIdx.x % BATCHN;
    const float4* h = (const float4*)(g_hist + ((size_t)t * BATCHN + b) * HID);
    const float4* w = (const float4*)Wout;
    float acc = 0.f;
    #pragma unroll
    for (int it = 0; it < 4; it++) {
        int k = it * 128 + threadIdx.x;
        float4 hv = h[k], wv = w[k];
        acc += hv.x * wv.x + hv.y * wv.y + hv.z * wv.z + hv.w * wv.w;
    }
    #pragma unroll
    for (int o = 16; o; o >>= 1) acc += __shfl_xor_sync(0xFFFFFFFFu, acc, o);
    __shared__ float ws[4];
    if ((threadIdx.x & 31) == 0) ws[threadIdx.x >> 5] = acc;
    __syncthreads();
    if (threadIdx.x == 0)
        out[b * NSTEPS + t] = ws[0] + ws[1] + ws[2] + ws[3] + bout[0];
}

// ---------------- launch ----------------
extern "C" void kernel_launch(void* const* d_in, const int* in_sizes, int n_in,
                              void* d_out, int out_size) {
    int wi = (n_in >= 8) ? 2 : 1;   // skip scalar `steps` input if present
    const float* tok  = (const float*)d_in[0];
    const float* Wih  = (const float*)d_in[wi];
    const float* Whh  = (const float*)d_in[wi + 1];
    const float* bih  = (const float*)d_in[wi + 2];
    const float* bhh  = (const float*)d_in[wi + 3];
    const float* Wout = (const float*)d_in[wi + 4];
    const float* bout = (const float*)d_in[wi + 5];
    float* out = (float*)d_out;

    cudaFuncSetAttribute(lstm_step, cudaFuncAttributeMaxDynamicSharedMemorySize, SMEM_REQ);

    prep_weights<<<32768, 256>>>(Wih, Whh);
    prep_misc<<<512, 256>>>(tok, bih, bhh);
    for (int t = 0; t < NSTEPS; t++)
        lstm_step<<<NTILE, 512, SMEM_REQ>>>(t);
    out_kernel<<<NSTEPS * BATCHN, 128>>>(Wout, bout, out);
}